// round 15
// baseline (speedup 1.0000x reference)
#include <cuda_runtime.h>
#include <cstdint>

#define NB 128
#define CIN 256
#define HH 28
#define WW 28
#define HWPIX 784
#define PPOS 900        // 30x30 padded positions
#define TAPS 9
#define CW 8            // 256 ch / 32 bits

// scratch — zero-initialized at module load; border of g_xpack is never written,
// so it stays zero across all calls (interior rewritten every call).
__device__ __align__(16) uint32_t g_xpack[(size_t)NB * PPOS * CW];   // [n][pos][word]
__device__ __align__(16) uint32_t g_wpack[CIN * TAPS * CW];          // [co][tap][word]
__device__ float g_scale2[CIN];            // -2 * gamma/sqrt(var+eps)
__device__ float g_bias2[9 * CIN];         // per boundary-class fused bias

// ---------------- merged prep ----------------
// grid = NB*HH (pack_x role, 224 threads used) + CIN (pack_w+BN role, 72 threads used)
#define PACKX_BLOCKS (NB * HH)
__global__ __launch_bounds__(224)
void prep_kernel(const float* __restrict__ x, const float* __restrict__ w,
                 const float* __restrict__ gamma, const float* __restrict__ beta,
                 const float* __restrict__ mean, const float* __restrict__ var) {
    int b = blockIdx.x;
    if (b < PACKX_BLOCKS) {
        // ---- pack_x role ----
        int n = b / HH, hh = b % HH;
        int word = threadIdx.x / 28, ww = threadIdx.x % 28;
        const float* xp = x + ((size_t)(n * CIN + word * 32) * HH + hh) * WW + ww;
        uint32_t bits = 0;
#pragma unroll
        for (int i = 0; i < 32; i++) {
            float v = xp[(size_t)i * HWPIX];
            bits |= (v < 0.f ? 1u : 0u) << i;
        }
        g_xpack[((size_t)n * PPOS + (hh + 1) * 30 + (ww + 1)) * CW + word] = bits;
        return;
    }
    // ---- pack_w + BN role ----
    __shared__ int s_pc[72];
    __shared__ int s_negw[TAPS];
    int co = b - PACKX_BLOCKS;
    int tid = threadIdx.x;
    if (tid < 72) {
        int tap = tid / 8, word = tid % 8;
        uint32_t bits = 0;
#pragma unroll
        for (int i = 0; i < 32; i++) {
            float v = w[((size_t)(co * CIN + word * 32 + i)) * TAPS + tap];
            bits |= (v < 0.f ? 1u : 0u) << i;
        }
        g_wpack[(co * TAPS + tap) * CW + word] = bits;
        s_pc[tid] = __popc(bits);
    }
    __syncthreads();
    if (tid < TAPS) {
        int s = 0;
#pragma unroll
        for (int wd = 0; wd < CW; wd++) s += s_pc[tid * 8 + wd];
        s_negw[tid] = s;
    }
    __syncthreads();
    if (tid < 9) {   // tid = boundary class hv*3+wv
        int hv = tid / 3, wv = tid % 3;
        float inv = gamma[co] * rsqrtf(var[co] + 1e-5f);
        float bias = beta[co] - mean[co] * inv;
        int nv = 0, s = 0;
#pragma unroll
        for (int kh = 0; kh < 3; kh++) {
#pragma unroll
            for (int kw = 0; kw < 3; kw++) {
                bool inval = (hv == 0 && kh == 0) || (hv == 2 && kh == 2) ||
                             (wv == 0 && kw == 0) || (wv == 2 && kw == 2);
                if (inval) s += s_negw[kh * 3 + kw];
                else nv++;
            }
        }
        float convBase = 256.f * nv + 2.f * (float)s;
        g_bias2[tid * CIN + co] = convBase * inv + bias;
        if (tid == 0) g_scale2[co] = -2.f * inv;
    }
}

// full adder (3:2 compressor): 2 LOP3
__device__ __forceinline__ void fa(uint32_t a, uint32_t b, uint32_t c,
                                   uint32_t& s, uint32_t& cy) {
    s = a ^ b ^ c;
    cy = (a & b) | (c & (a | b));
}

// 12-word popcount, f=3 CSA tree — measured optimum of the f-sweep
// (f=0:395us, f=3:331us, f=5:340us, f=7:374us conv time).
__device__ __forceinline__ int popc12(const uint32_t* e) {
    uint32_t s0, c0, s1, c1, s2, c2;
    fa(e[0], e[1], e[2], s0, c0);
    fa(e[3], e[4], e[5], s1, c1);
    fa(e[6], e[7], e[8], s2, c2);
    int w1 = __popc(s0) + __popc(s1) + __popc(s2)
           + __popc(e[9]) + __popc(e[10]) + __popc(e[11]);
    int w2 = __popc(c0) + __popc(c1) + __popc(c2);
    return w1 + w2 * 2;
}

// ---------------- main conv ----------------
// grid (NB, 16 co-groups of 16, 2 row-halves), block 224 = 4 cog4 x 56 pixel-threads
// thread: 7 pixels (quarter row) x 4 co (2 packed pairs); block covers 14 rows x 16 co
#define XROWS 16   // 14 output rows + 2 halo
__global__ __launch_bounds__(224, 3)
void popc_conv_kernel(const float* __restrict__ x, float* __restrict__ out) {
    __shared__ uint32_t s_x[XROWS * 30 * CW];   // 15360 B
    __shared__ uint32_t s_w[16 * TAPS * CW];    // 4608 B
    int tid = threadIdx.x;
    int n = blockIdx.x, cg16 = blockIdx.y, rh = blockIdx.z;

    {
        const uint4* xs = (const uint4*)(g_xpack + ((size_t)n * PPOS + rh * 14 * 30) * CW);
        uint4* xd = (uint4*)s_x;
        for (int i = tid; i < XROWS * 30 * CW / 4; i += 224) xd[i] = xs[i];
        const uint4* ws = (const uint4*)(g_wpack + (size_t)cg16 * 16 * TAPS * CW);
        uint4* wd = (uint4*)s_w;
        for (int i = tid; i < 16 * TAPS * CW / 4; i += 224) wd[i] = ws[i];
    }
    __syncthreads();

    int cog4 = tid / 56, q = tid % 56;
    int hl = q >> 2, w0 = 7 * (q & 3);
    int h = rh * 14 + hl;

    int acc[7][2];   // [pixel][co-pair], lo16 = even co, hi16 = odd co
#pragma unroll
    for (int p = 0; p < 7; p++) {
        acc[p][0] = 0; acc[p][1] = 0;
    }

#pragma unroll 1
    for (int kh = 0; kh < 3; kh++) {
        // wv fully unrolled: two independent LDS->XOR->CSA chains in flight
        // per warp iteration (double ILP at unchanged instruction count).
#pragma unroll
        for (int wv = 0; wv < 2; wv++) {
            uint4 xq[9];
            int xbase = ((hl + kh) * 30 + w0) * CW + wv * 4;
#pragma unroll
            for (int i = 0; i < 9; i++)
                xq[i] = *(const uint4*)&s_x[xbase + i * CW];
#pragma unroll
            for (int cp = 0; cp < 2; cp++) {
                uint4 wqa[3], wqb[3];
                int wbase = ((cog4 * 4 + cp * 2) * TAPS + kh * 3) * CW + wv * 4;
#pragma unroll
                for (int kw = 0; kw < 3; kw++) {
                    wqa[kw] = *(const uint4*)&s_w[wbase + kw * CW];
                    wqb[kw] = *(const uint4*)&s_w[wbase + TAPS * CW + kw * CW];
                }
#pragma unroll
                for (int p = 0; p < 7; p++) {
                    uint32_t ea[12], eb[12];
#pragma unroll
                    for (int kw = 0; kw < 3; kw++) {
                        uint4 xv = xq[p + kw];
                        ea[kw * 4 + 0] = xv.x ^ wqa[kw].x;
                        ea[kw * 4 + 1] = xv.y ^ wqa[kw].y;
                        ea[kw * 4 + 2] = xv.z ^ wqa[kw].z;
                        ea[kw * 4 + 3] = xv.w ^ wqa[kw].w;
                        eb[kw * 4 + 0] = xv.x ^ wqb[kw].x;
                        eb[kw * 4 + 1] = xv.y ^ wqb[kw].y;
                        eb[kw * 4 + 2] = xv.z ^ wqb[kw].z;
                        eb[kw * 4 + 3] = xv.w ^ wqb[kw].w;
                    }
                    int ta = popc12(ea);
                    int tb = popc12(eb);
                    acc[p][cp] += ta + tb * 65536;   // IMAD -> fma pipe
                }
            }
        }
    }

    // epilogue: fused BN (+ boundary correction) + hardtanh + residual
    int hv = (h == 0) ? 0 : (h == 27 ? 2 : 1);
    int co_base = cg16 * 16 + cog4 * 4;
#pragma unroll
    for (int p = 0; p < 7; p++) {
        int w = w0 + p;
        int wvc = (w == 0) ? 0 : (w == 27 ? 2 : 1);
        int cls = hv * 3 + wvc;
#pragma unroll
        for (int cp = 0; cp < 2; cp++) {
            int ca = acc[p][cp] & 0xFFFF;
            int cb = acc[p][cp] >> 16;
            int co = co_base + cp * 2;
            float s2a = __ldg(g_scale2 + co), s2b = __ldg(g_scale2 + co + 1);
            float b2a = __ldg(g_bias2 + cls * CIN + co);
            float b2b = __ldg(g_bias2 + cls * CIN + co + 1);
            float va = fminf(fmaxf(fmaf((float)ca, s2a, b2a), -1.f), 1.f);
            float vb = fminf(fmaxf(fmaf((float)cb, s2b, b2b), -1.f), 1.f);
            size_t idx = ((size_t)(n * CIN + co)) * HWPIX + h * WW + w;
            out[idx] = va + x[idx];
            out[idx + HWPIX] = vb + x[idx + HWPIX];
        }
    }
}

// ---------------- launch ----------------
extern "C" void kernel_launch(void* const* d_in, const int* in_sizes, int n_in,
                              void* d_out, int out_size) {
    const float* x     = (const float*)d_in[0];
    const float* w     = (const float*)d_in[1];
    const float* gamma = (const float*)d_in[2];
    const float* beta  = (const float*)d_in[3];
    const float* rmean = (const float*)d_in[4];
    const float* rvar  = (const float*)d_in[5];
    float* out = (float*)d_out;

    prep_kernel<<<PACKX_BLOCKS + CIN, 224>>>(x, w, gamma, beta, rmean, rvar); // launch 0
    popc_conv_kernel<<<dim3(NB, 16, 2), 224>>>(x, out);                       // launch 1
}

// round 16
// speedup vs baseline: 1.0731x; 1.0731x over previous
#include <cuda_runtime.h>
#include <cstdint>

#define NB 128
#define CIN 256
#define HH 28
#define WW 28
#define HWPIX 784
#define PPOS 900        // 30x30 padded positions
#define TAPS 9
#define CW 8            // 256 ch / 32 bits

// scratch — zero-initialized at module load; border of g_xpack is never written,
// so it stays zero across all calls (interior rewritten every call).
__device__ __align__(16) uint32_t g_xpack[(size_t)NB * PPOS * CW];   // [n][pos][word]
__device__ __align__(16) uint32_t g_wpack[CIN * TAPS * CW];          // [co][tap][word]
__device__ float g_scale2[CIN];            // -2 * gamma/sqrt(var+eps)
__device__ float g_bias2[9 * CIN];         // per boundary-class fused bias

// ---------------- merged prep ----------------
// grid = NB*HH (pack_x role, 224 threads used) + CIN (pack_w+BN role, 72 threads used)
#define PACKX_BLOCKS (NB * HH)
__global__ __launch_bounds__(224)
void prep_kernel(const float* __restrict__ x, const float* __restrict__ w,
                 const float* __restrict__ gamma, const float* __restrict__ beta,
                 const float* __restrict__ mean, const float* __restrict__ var) {
    int b = blockIdx.x;
    if (b < PACKX_BLOCKS) {
        // ---- pack_x role ----
        int n = b / HH, hh = b % HH;
        int word = threadIdx.x / 28, ww = threadIdx.x % 28;
        const float* xp = x + ((size_t)(n * CIN + word * 32) * HH + hh) * WW + ww;
        uint32_t bits = 0;
#pragma unroll
        for (int i = 0; i < 32; i++) {
            float v = xp[(size_t)i * HWPIX];
            bits |= (v < 0.f ? 1u : 0u) << i;
        }
        g_xpack[((size_t)n * PPOS + (hh + 1) * 30 + (ww + 1)) * CW + word] = bits;
        return;
    }
    // ---- pack_w + BN role ----
    __shared__ int s_pc[72];
    __shared__ int s_negw[TAPS];
    int co = b - PACKX_BLOCKS;
    int tid = threadIdx.x;
    if (tid < 72) {
        int tap = tid / 8, word = tid % 8;
        uint32_t bits = 0;
#pragma unroll
        for (int i = 0; i < 32; i++) {
            float v = w[((size_t)(co * CIN + word * 32 + i)) * TAPS + tap];
            bits |= (v < 0.f ? 1u : 0u) << i;
        }
        g_wpack[(co * TAPS + tap) * CW + word] = bits;
        s_pc[tid] = __popc(bits);
    }
    __syncthreads();
    if (tid < TAPS) {
        int s = 0;
#pragma unroll
        for (int wd = 0; wd < CW; wd++) s += s_pc[tid * 8 + wd];
        s_negw[tid] = s;
    }
    __syncthreads();
    if (tid < 9) {   // tid = boundary class hv*3+wv
        int hv = tid / 3, wv = tid % 3;
        float inv = gamma[co] * rsqrtf(var[co] + 1e-5f);
        float bias = beta[co] - mean[co] * inv;
        int nv = 0, s = 0;
#pragma unroll
        for (int kh = 0; kh < 3; kh++) {
#pragma unroll
            for (int kw = 0; kw < 3; kw++) {
                bool inval = (hv == 0 && kh == 0) || (hv == 2 && kh == 2) ||
                             (wv == 0 && kw == 0) || (wv == 2 && kw == 2);
                if (inval) s += s_negw[kh * 3 + kw];
                else nv++;
            }
        }
        float convBase = 256.f * nv + 2.f * (float)s;
        g_bias2[tid * CIN + co] = convBase * inv + bias;
        if (tid == 0) g_scale2[co] = -2.f * inv;
    }
}

// full adder (3:2 compressor): 2 LOP3
__device__ __forceinline__ void fa(uint32_t a, uint32_t b, uint32_t c,
                                   uint32_t& s, uint32_t& cy) {
    s = a ^ b ^ c;
    cy = (a & b) | (c & (a | b));
}

// 12-word popcount, f=3 CSA tree — measured optimum of the f-sweep
// (f=0:395us, f=3:331us, f=5:340us, f=7:374us conv time).
__device__ __forceinline__ int popc12(const uint32_t* e) {
    uint32_t s0, c0, s1, c1, s2, c2;
    fa(e[0], e[1], e[2], s0, c0);
    fa(e[3], e[4], e[5], s1, c1);
    fa(e[6], e[7], e[8], s2, c2);
    int w1 = __popc(s0) + __popc(s1) + __popc(s2)
           + __popc(e[9]) + __popc(e[10]) + __popc(e[11]);
    int w2 = __popc(c0) + __popc(c1) + __popc(c2);
    return w1 + w2 * 2;
}

// ---------------- main conv ----------------
// grid (NB, 16 co-groups of 16, 2 row-halves), block 224 = 4 cog4 x 56 pixel-threads
// thread: 7 pixels (quarter row) x 4 co (2 packed pairs); block covers 14 rows x 16 co
#define XROWS 16   // 14 output rows + 2 halo
__global__ __launch_bounds__(224, 3)
void popc_conv_kernel(const float* __restrict__ x, float* __restrict__ out) {
    __shared__ uint32_t s_x[XROWS * 30 * CW];   // 15360 B
    __shared__ uint32_t s_w[16 * TAPS * CW];    // 4608 B
    int tid = threadIdx.x;
    int n = blockIdx.x, cg16 = blockIdx.y, rh = blockIdx.z;

    {
        const uint4* xs = (const uint4*)(g_xpack + ((size_t)n * PPOS + rh * 14 * 30) * CW);
        uint4* xd = (uint4*)s_x;
        for (int i = tid; i < XROWS * 30 * CW / 4; i += 224) xd[i] = xs[i];
        const uint4* ws = (const uint4*)(g_wpack + (size_t)cg16 * 16 * TAPS * CW);
        uint4* wd = (uint4*)s_w;
        for (int i = tid; i < 16 * TAPS * CW / 4; i += 224) wd[i] = ws[i];
    }
    __syncthreads();

    int cog4 = tid / 56, q = tid % 56;
    int hl = q >> 2, w0 = 7 * (q & 3);
    int h = rh * 14 + hl;

    int acc[7][2];   // [pixel][co-pair], lo16 = even co, hi16 = odd co
#pragma unroll
    for (int p = 0; p < 7; p++) {
        acc[p][0] = 0; acc[p][1] = 0;
    }

#pragma unroll 1
    for (int kh = 0; kh < 3; kh++) {
#pragma unroll 1
        for (int wv = 0; wv < 2; wv++) {
            uint4 xq[9];
            int xbase = ((hl + kh) * 30 + w0) * CW + wv * 4;
#pragma unroll
            for (int i = 0; i < 9; i++)
                xq[i] = *(const uint4*)&s_x[xbase + i * CW];
#pragma unroll
            for (int cp = 0; cp < 2; cp++) {
                uint4 wqa[3], wqb[3];
                int wbase = ((cog4 * 4 + cp * 2) * TAPS + kh * 3) * CW + wv * 4;
#pragma unroll
                for (int kw = 0; kw < 3; kw++) {
                    wqa[kw] = *(const uint4*)&s_w[wbase + kw * CW];
                    wqb[kw] = *(const uint4*)&s_w[wbase + TAPS * CW + kw * CW];
                }
#pragma unroll
                for (int p = 0; p < 7; p++) {
                    uint32_t ea[12], eb[12];
#pragma unroll
                    for (int kw = 0; kw < 3; kw++) {
                        uint4 xv = xq[p + kw];
                        ea[kw * 4 + 0] = xv.x ^ wqa[kw].x;
                        ea[kw * 4 + 1] = xv.y ^ wqa[kw].y;
                        ea[kw * 4 + 2] = xv.z ^ wqa[kw].z;
                        ea[kw * 4 + 3] = xv.w ^ wqa[kw].w;
                        eb[kw * 4 + 0] = xv.x ^ wqb[kw].x;
                        eb[kw * 4 + 1] = xv.y ^ wqb[kw].y;
                        eb[kw * 4 + 2] = xv.z ^ wqb[kw].z;
                        eb[kw * 4 + 3] = xv.w ^ wqb[kw].w;
                    }
                    int ta = popc12(ea);
                    int tb = popc12(eb);
                    acc[p][cp] += ta + tb * 65536;   // IMAD -> fma pipe
                }
            }
        }
    }

    // epilogue: fused BN (+ boundary correction) + hardtanh + residual
    int hv = (h == 0) ? 0 : (h == 27 ? 2 : 1);
    int co_base = cg16 * 16 + cog4 * 4;
#pragma unroll
    for (int p = 0; p < 7; p++) {
        int w = w0 + p;
        int wvc = (w == 0) ? 0 : (w == 27 ? 2 : 1);
        int cls = hv * 3 + wvc;
#pragma unroll
        for (int cp = 0; cp < 2; cp++) {
            int ca = acc[p][cp] & 0xFFFF;
            int cb = acc[p][cp] >> 16;
            int co = co_base + cp * 2;
            float s2a = __ldg(g_scale2 + co), s2b = __ldg(g_scale2 + co + 1);
            float b2a = __ldg(g_bias2 + cls * CIN + co);
            float b2b = __ldg(g_bias2 + cls * CIN + co + 1);
            float va = fminf(fmaxf(fmaf((float)ca, s2a, b2a), -1.f), 1.f);
            float vb = fminf(fmaxf(fmaf((float)cb, s2b, b2b), -1.f), 1.f);
            size_t idx = ((size_t)(n * CIN + co)) * HWPIX + h * WW + w;
            out[idx] = va + x[idx];
            out[idx + HWPIX] = vb + x[idx + HWPIX];
        }
    }
}

// ---------------- launch ----------------
extern "C" void kernel_launch(void* const* d_in, const int* in_sizes, int n_in,
                              void* d_out, int out_size) {
    const float* x     = (const float*)d_in[0];
    const float* w     = (const float*)d_in[1];
    const float* gamma = (const float*)d_in[2];
    const float* beta  = (const float*)d_in[3];
    const float* rmean = (const float*)d_in[4];
    const float* rvar  = (const float*)d_in[5];
    float* out = (float*)d_out;

    prep_kernel<<<PACKX_BLOCKS + CIN, 224>>>(x, w, gamma, beta, rmean, rvar); // launch 0
    popc_conv_kernel<<<dim3(NB, 16, 2), 224>>>(x, out);                       // launch 1
}

// round 17
// speedup vs baseline: 1.0806x; 1.0070x over previous
#include <cuda_runtime.h>
#include <cstdint>

#define NB 128
#define CIN 256
#define HH 28
#define WW 28
#define HWPIX 784
#define PPOS 900        // 30x30 padded positions
#define TAPS 9
#define CW 8            // 256 ch / 32 bits

// scratch — zero-initialized at module load; border of g_xpack is never written,
// so it stays zero across all calls (interior rewritten every call).
__device__ __align__(16) uint32_t g_xpack[(size_t)NB * PPOS * CW];   // [n][pos][word]
__device__ __align__(16) uint32_t g_wpack[CIN * TAPS * CW];          // [co][tap][word]
__device__ float g_scale2[CIN];            // -2 * gamma/sqrt(var+eps)
__device__ float g_bias2[9 * CIN];         // per boundary-class fused bias

// ---------------- merged prep ----------------
// grid = NB*HH (pack_x role, 224 threads used) + CIN (pack_w+BN role, 72 threads used)
#define PACKX_BLOCKS (NB * HH)
__global__ __launch_bounds__(224)
void prep_kernel(const float* __restrict__ x, const float* __restrict__ w,
                 const float* __restrict__ gamma, const float* __restrict__ beta,
                 const float* __restrict__ mean, const float* __restrict__ var) {
    int b = blockIdx.x;
    if (b < PACKX_BLOCKS) {
        // ---- pack_x role ----
        int n = b / HH, hh = b % HH;
        int word = threadIdx.x / 28, ww = threadIdx.x % 28;
        const float* xp = x + ((size_t)(n * CIN + word * 32) * HH + hh) * WW + ww;
        uint32_t bits = 0;
#pragma unroll
        for (int i = 0; i < 32; i++) {
            float v = xp[(size_t)i * HWPIX];
            bits |= (v < 0.f ? 1u : 0u) << i;
        }
        g_xpack[((size_t)n * PPOS + (hh + 1) * 30 + (ww + 1)) * CW + word] = bits;
        return;
    }
    // ---- pack_w + BN role ----
    __shared__ int s_pc[72];
    __shared__ int s_negw[TAPS];
    int co = b - PACKX_BLOCKS;
    int tid = threadIdx.x;
    if (tid < 72) {
        int tap = tid / 8, word = tid % 8;
        uint32_t bits = 0;
#pragma unroll
        for (int i = 0; i < 32; i++) {
            float v = w[((size_t)(co * CIN + word * 32 + i)) * TAPS + tap];
            bits |= (v < 0.f ? 1u : 0u) << i;
        }
        g_wpack[(co * TAPS + tap) * CW + word] = bits;
        s_pc[tid] = __popc(bits);
    }
    __syncthreads();
    if (tid < TAPS) {
        int s = 0;
#pragma unroll
        for (int wd = 0; wd < CW; wd++) s += s_pc[tid * 8 + wd];
        s_negw[tid] = s;
    }
    __syncthreads();
    if (tid < 9) {   // tid = boundary class hv*3+wv
        int hv = tid / 3, wv = tid % 3;
        float inv = gamma[co] * rsqrtf(var[co] + 1e-5f);
        float bias = beta[co] - mean[co] * inv;
        int nv = 0, s = 0;
#pragma unroll
        for (int kh = 0; kh < 3; kh++) {
#pragma unroll
            for (int kw = 0; kw < 3; kw++) {
                bool inval = (hv == 0 && kh == 0) || (hv == 2 && kh == 2) ||
                             (wv == 0 && kw == 0) || (wv == 2 && kw == 2);
                if (inval) s += s_negw[kh * 3 + kw];
                else nv++;
            }
        }
        float convBase = 256.f * nv + 2.f * (float)s;
        g_bias2[tid * CIN + co] = convBase * inv + bias;
        if (tid == 0) g_scale2[co] = -2.f * inv;
    }
}

// full adder (3:2 compressor): 2 LOP3
__device__ __forceinline__ void fa(uint32_t a, uint32_t b, uint32_t c,
                                   uint32_t& s, uint32_t& cy) {
    s = a ^ b ^ c;
    cy = (a & b) | (c & (a | b));
}

// 12-word popcount, f=3 CSA tree — measured optimum of the f-sweep
// (f=0:395us, f=3:331us, f=5:340us, f=7:374us conv time).
__device__ __forceinline__ int popc12(const uint32_t* e) {
    uint32_t s0, c0, s1, c1, s2, c2;
    fa(e[0], e[1], e[2], s0, c0);
    fa(e[3], e[4], e[5], s1, c1);
    fa(e[6], e[7], e[8], s2, c2);
    int w1 = __popc(s0) + __popc(s1) + __popc(s2)
           + __popc(e[9]) + __popc(e[10]) + __popc(e[11]);
    int w2 = __popc(c0) + __popc(c1) + __popc(c2);
    return w1 + w2 * 2;
}

// ---------------- main conv ----------------
// grid (NB, 16 co-groups of 16, 2 row-halves), block 224 = 4 cog4 x 56 pixel-threads
// thread: 7 pixels (quarter row) x 4 co (2 packed pairs); block covers 14 rows x 16 co
// Identical body to the measured optimum; only the reg cap changes (80 -> 72) to
// unlock the 4th CTA per SM.
#define XROWS 16   // 14 output rows + 2 halo
__global__ __launch_bounds__(224, 4)
void popc_conv_kernel(const float* __restrict__ x, float* __restrict__ out) {
    __shared__ uint32_t s_x[XROWS * 30 * CW];   // 15360 B
    __shared__ uint32_t s_w[16 * TAPS * CW];    // 4608 B
    int tid = threadIdx.x;
    int n = blockIdx.x, cg16 = blockIdx.y, rh = blockIdx.z;

    {
        const uint4* xs = (const uint4*)(g_xpack + ((size_t)n * PPOS + rh * 14 * 30) * CW);
        uint4* xd = (uint4*)s_x;
        for (int i = tid; i < XROWS * 30 * CW / 4; i += 224) xd[i] = xs[i];
        const uint4* ws = (const uint4*)(g_wpack + (size_t)cg16 * 16 * TAPS * CW);
        uint4* wd = (uint4*)s_w;
        for (int i = tid; i < 16 * TAPS * CW / 4; i += 224) wd[i] = ws[i];
    }
    __syncthreads();

    int cog4 = tid / 56, q = tid % 56;
    int hl = q >> 2, w0 = 7 * (q & 3);
    int h = rh * 14 + hl;

    int acc[7][2];   // [pixel][co-pair], lo16 = even co, hi16 = odd co
#pragma unroll
    for (int p = 0; p < 7; p++) {
        acc[p][0] = 0; acc[p][1] = 0;
    }

#pragma unroll 1
    for (int kh = 0; kh < 3; kh++) {
#pragma unroll 1
        for (int wv = 0; wv < 2; wv++) {
            uint4 xq[9];
            int xbase = ((hl + kh) * 30 + w0) * CW + wv * 4;
#pragma unroll
            for (int i = 0; i < 9; i++)
                xq[i] = *(const uint4*)&s_x[xbase + i * CW];
#pragma unroll
            for (int cp = 0; cp < 2; cp++) {
                uint4 wqa[3], wqb[3];
                int wbase = ((cog4 * 4 + cp * 2) * TAPS + kh * 3) * CW + wv * 4;
#pragma unroll
                for (int kw = 0; kw < 3; kw++) {
                    wqa[kw] = *(const uint4*)&s_w[wbase + kw * CW];
                    wqb[kw] = *(const uint4*)&s_w[wbase + TAPS * CW + kw * CW];
                }
#pragma unroll
                for (int p = 0; p < 7; p++) {
                    uint32_t ea[12], eb[12];
#pragma unroll
                    for (int kw = 0; kw < 3; kw++) {
                        uint4 xv = xq[p + kw];
                        ea[kw * 4 + 0] = xv.x ^ wqa[kw].x;
                        ea[kw * 4 + 1] = xv.y ^ wqa[kw].y;
                        ea[kw * 4 + 2] = xv.z ^ wqa[kw].z;
                        ea[kw * 4 + 3] = xv.w ^ wqa[kw].w;
                        eb[kw * 4 + 0] = xv.x ^ wqb[kw].x;
                        eb[kw * 4 + 1] = xv.y ^ wqb[kw].y;
                        eb[kw * 4 + 2] = xv.z ^ wqb[kw].z;
                        eb[kw * 4 + 3] = xv.w ^ wqb[kw].w;
                    }
                    int ta = popc12(ea);
                    int tb = popc12(eb);
                    acc[p][cp] += ta + tb * 65536;   // IMAD -> fma pipe
                }
            }
        }
    }

    // epilogue: fused BN (+ boundary correction) + hardtanh + residual
    int hv = (h == 0) ? 0 : (h == 27 ? 2 : 1);
    int co_base = cg16 * 16 + cog4 * 4;
#pragma unroll
    for (int p = 0; p < 7; p++) {
        int w = w0 + p;
        int wvc = (w == 0) ? 0 : (w == 27 ? 2 : 1);
        int cls = hv * 3 + wvc;
#pragma unroll
        for (int cp = 0; cp < 2; cp++) {
            int ca = acc[p][cp] & 0xFFFF;
            int cb = acc[p][cp] >> 16;
            int co = co_base + cp * 2;
            float s2a = __ldg(g_scale2 + co), s2b = __ldg(g_scale2 + co + 1);
            float b2a = __ldg(g_bias2 + cls * CIN + co);
            float b2b = __ldg(g_bias2 + cls * CIN + co + 1);
            float va = fminf(fmaxf(fmaf((float)ca, s2a, b2a), -1.f), 1.f);
            float vb = fminf(fmaxf(fmaf((float)cb, s2b, b2b), -1.f), 1.f);
            size_t idx = ((size_t)(n * CIN + co)) * HWPIX + h * WW + w;
            out[idx] = va + x[idx];
            out[idx + HWPIX] = vb + x[idx + HWPIX];
        }
    }
}

// ---------------- launch ----------------
extern "C" void kernel_launch(void* const* d_in, const int* in_sizes, int n_in,
                              void* d_out, int out_size) {
    const float* x     = (const float*)d_in[0];
    const float* w     = (const float*)d_in[1];
    const float* gamma = (const float*)d_in[2];
    const float* beta  = (const float*)d_in[3];
    const float* rmean = (const float*)d_in[4];
    const float* rvar  = (const float*)d_in[5];
    float* out = (float*)d_out;

    prep_kernel<<<PACKX_BLOCKS + CIN, 224>>>(x, w, gamma, beta, rmean, rvar); // launch 0
    popc_conv_kernel<<<dim3(NB, 16, 2), 224>>>(x, out);                       // launch 1
}